// round 13
// baseline (speedup 1.0000x reference)
#include <cuda_runtime.h>
#include <cuda_bf16.h>
#include <cstdint>

// ---------------------------------------------------------------------------
// YOLO loss (nc=1).  B=64, N=32, A=3, grids {160,80,40}, pred [B,18,G,G].
//
// loss = 0.05 * sum_s box_sq[s]/n_pos[s]
//      +        sum_s ( pos_plus[s]/n_pos[s] + (S_all[s]-pos_neg[s])/n_neg[s] )
//
// R3-R11: e2e pinned at ~25.2us = 25.8MB / ~1TB/s regardless of kernel shape
// -> L2 is not retaining the 25.8MB obj working set across graph replays.
// This round: dense loads via 32-byte ld.global.nc.L2::evict_last.v4.b64
// (sm_103 requires v8.b32/v4.b64 with evict_last) -> pin obj channel in L2;
// bonus: half the load instructions (one 32B load per accum8).
// ---------------------------------------------------------------------------

#define NN 32
#define TGT_BLOCKS 24
#define NB0D 384
#define NB1D 96
#define NB2D 24
#define DENSE_BLOCKS (NB0D + NB1D + NB2D)          // 504
#define TOTAL_BLOCKS (TGT_BLOCKS + DENSE_BLOCKS)   // 528

__device__ double   g_part[DENSE_BLOCKS];  // dense per-block partials
__device__ float4   g_tpart[192];          // target partials: sq, sp-, sp+, cnt
__device__ unsigned g_ticket;

__device__ __forceinline__ float ex2f(float x) {
    float r; asm("ex2.approx.f32 %0, %1;" : "=f"(r) : "f"(x)); return r;
}
__device__ __forceinline__ float lg2f(float x) {
    float r; asm("lg2.approx.f32 %0, %1;" : "=f"(r) : "f"(x)); return r;
}

struct F8 { float x0, x1, x2, x3, x4, x5, x6, x7; };

// 32-byte L2-pinned load (v4.b64 is the required shape for evict_last on sm_103)
__device__ __forceinline__ F8 ldg_el8(const void* p) {
    unsigned long long r0, r1, r2, r3;
    asm("ld.global.nc.L2::evict_last.v4.b64 {%0,%1,%2,%3}, [%4];"
        : "=l"(r0), "=l"(r1), "=l"(r2), "=l"(r3) : "l"(p));
    F8 v;
    v.x0 = __uint_as_float((unsigned)r0);  v.x1 = __uint_as_float((unsigned)(r0 >> 32));
    v.x2 = __uint_as_float((unsigned)r1);  v.x3 = __uint_as_float((unsigned)(r1 >> 32));
    v.x4 = __uint_as_float((unsigned)r2);  v.x5 = __uint_as_float((unsigned)(r2 >> 32));
    v.x6 = __uint_as_float((unsigned)r3);  v.x7 = __uint_as_float((unsigned)(r3 >> 32));
    return v;
}

__device__ __forceinline__ float sp(float x) {   // target pass only
    return fmaxf(x, 0.0f) + __logf(1.0f + __expf(-fabsf(x)));
}

struct Acc { float ax0, ax1, au0, au1, alg0, alg1; };

#define NL2E (-1.4426950408889634f)

// 8 elements -> 8 EX2 + 1 LG2  (validated rel_err 0.0 since R10)
__device__ __forceinline__ void accum8(F8 a, Acc& c) {
    float u0 = fabsf(a.x0), u1 = fabsf(a.x1), u2 = fabsf(a.x2), u3 = fabsf(a.x3);
    float u4 = fabsf(a.x4), u5 = fabsf(a.x5), u6 = fabsf(a.x6), u7 = fabsf(a.x7);
    float e0 = ex2f(u0 * NL2E), e1 = ex2f(u1 * NL2E);
    float e2 = ex2f(u2 * NL2E), e3 = ex2f(u3 * NL2E);
    float e4 = ex2f(u4 * NL2E), e5 = ex2f(u5 * NL2E);
    float e6 = ex2f(u6 * NL2E), e7 = ex2f(u7 * NL2E);
    float p0 = 1.0f + e0;
    p0 = fmaf(p0, e1, p0);
    p0 = fmaf(p0, e2, p0);
    p0 = fmaf(p0, e3, p0);
    float p1 = 1.0f + e4;
    p1 = fmaf(p1, e5, p1);
    p1 = fmaf(p1, e6, p1);
    p1 = fmaf(p1, e7, p1);
    c.alg0 += lg2f(p0 * p1);
    c.ax0 += (a.x0 + a.x1) + (a.x2 + a.x3);
    c.ax1 += (a.x4 + a.x5) + (a.x6 + a.x7);
    c.au0 += (u0 + u1) + (u2 + u3);
    c.au1 += (u4 + u5) + (u6 + u7);
}

// gathered obj f8 index -> physical byte pointer
// idx = p*HW8 + pos (p = b*3+a) ; phys_f8 = idx + 5*HW8*p + 4*HW8
template <int HW8>
__device__ __forceinline__ const char* objp8(const char* __restrict__ base, int idx) {
    int p = idx / HW8;                       // compile-time magic-mul
    return base + (size_t)(idx + (5 * HW8) * p + 4 * HW8) * 32;
}

// 1600 gathered f8 per block: rotating named-register pipeline (MLP~2x32B).
template <int HW8>
__device__ __forceinline__ void dense1600(const char* __restrict__ base,
                                          int gbase, int tid, Acc& c) {
    int g = gbase + tid;
    F8 a0 = ldg_el8(objp8<HW8>(base, g));
    F8 b0 = ldg_el8(objp8<HW8>(base, g + 256));
    #pragma unroll
    for (int k = 0; k < 2; k++) {
        F8 a1 = ldg_el8(objp8<HW8>(base, g + (2 * k + 2) * 256));
        F8 b1 = ldg_el8(objp8<HW8>(base, g + (2 * k + 3) * 256));
        accum8(a0, c);
        accum8(b0, c);
        a0 = a1; b0 = b1;
    }
    accum8(a0, c);
    accum8(b0, c);
    if (tid < 64)
        accum8(ldg_el8(objp8<HW8>(base, gbase + 1536 + tid)), c);
}

__global__ void __launch_bounds__(256, 4) yolo_kernel(
        const float* __restrict__ pred0,
        const float* __restrict__ pred1,
        const float* __restrict__ pred2,
        const float* __restrict__ boxes,
        const float* __restrict__ anchors,
        float* __restrict__ out) {
    const int bid  = blockIdx.x;
    const int tid  = threadIdx.x;
    const int lane = tid & 31;
    const int wid  = tid >> 5;

    __shared__ float  warpsum[8];
    __shared__ int    keys[8][NN];
    __shared__ double dsh[3][8];
    __shared__ double tsh[4][6];
    __shared__ bool   s_last;

    if (bid >= TGT_BLOCKS) {
        // ---------------- dense objectness pass ----------------
        const int d = bid - TGT_BLOCKS;
        Acc a = {0.0f, 0.0f, 0.0f, 0.0f, 0.0f, 0.0f};
        if (d < NB0D) {
            // HW8 for s0: 6400 f4 / 2 = 3200
            dense1600<3200>((const char*)pred0, d * 1600, tid, a);
        } else if (d < NB0D + NB1D) {
            dense1600< 800>((const char*)pred1, (d - NB0D) * 1600, tid, a);
        } else {
            dense1600< 200>((const char*)pred2, (d - NB0D - NB1D) * 1600, tid, a);
        }
        float v = 0.5f * ((a.ax0 + a.ax1) + (a.au0 + a.au1))
                + 0.69314718055994531f * (a.alg0 + a.alg1);

        #pragma unroll
        for (int o = 16; o > 0; o >>= 1)
            v += __shfl_down_sync(0xffffffffu, v, o);
        if (lane == 0) warpsum[wid] = v;
        __syncthreads();
        if (tid == 0) {
            double t = 0.0;
            #pragma unroll
            for (int w = 0; w < 8; w++) t += (double)warpsum[w];
            g_part[d] = t;
        }
    } else {
        // ---------------- sparse target pass: one (scale,batch) per warp ----------------
        const int task = bid * 8 + wid;          // 0..191
        const int s = task >> 6;
        const int b = task & 63;
        const int n = lane;

        const int G = (s == 0) ? 160 : (s == 1) ? 80 : 40;
        const float* pred = (s == 0) ? pred0 : (s == 1) ? pred1 : pred2;
        const int HW = G * G;

        float4 bx = reinterpret_cast<const float4*>(boxes)[b * NN + n];
        float gx = bx.x * (float)G;
        float gy = bx.y * (float)G;
        float gw = bx.z * (float)G;
        float gh = bx.w * (float)G;
        int gi = (int)gx;
        int gj = (int)gy;

        // anchor matching: argmax over a of prod(min(r,1/r)), first-max tiebreak
        float bestIou = -1.0f;
        float aw = 1.0f, ah = 1.0f;
        int best = 0;
        #pragma unroll
        for (int a = 0; a < 3; a++) {
            float Aw = anchors[s * 6 + a * 2 + 0];
            float Ah = anchors[s * 6 + a * 2 + 1];
            float rw = __fdiv_rn(Aw, gw);
            float rh = __fdiv_rn(Ah, gh);
            float iw = fminf(rw, __fdiv_rn(1.0f, rw));
            float ih = fminf(rh, __fdiv_rn(1.0f, rh));
            float iou = iw * ih;
            if (iou > bestIou) { bestIou = iou; best = a; aw = Aw; ah = Ah; }
        }

        // dedup: last write wins -> entry n live iff no later n' has same key
        int key = (best * G + gj) * G + gi;
        keys[wid][n] = key;
        __syncwarp();
        bool live = true;
        for (int m = n + 1; m < NN; m++)
            if (keys[wid][m] == key) { live = false; break; }

        float sq = 0.0f, spp = 0.0f, spm = 0.0f, cnt = 0.0f;
        if (live) {
            size_t base = (size_t)(b * 18 + best * 6) * HW + (size_t)gj * G + gi;
            float p0 = __ldg(pred + base);
            float p1 = __ldg(pred + base + (size_t)HW);
            float p2 = __ldg(pred + base + (size_t)2 * HW);
            float p3 = __ldg(pred + base + (size_t)3 * HW);
            float p4 = __ldg(pred + base + (size_t)4 * HW);

            float tx = gx - (float)gi;
            float ty = gy - (float)gj;
            float tw = logf(__fdiv_rn(gw, aw) + 1e-16f);
            float th = logf(__fdiv_rn(gh, ah) + 1e-16f);

            float d0 = p0 - tx, d1 = p1 - ty, d2 = p2 - tw, d3 = p3 - th;
            sq  = d0 * d0 + d1 * d1 + d2 * d2 + d3 * d3;
            spm = sp(-p4);
            spp = sp(p4);
            cnt = 1.0f;
        }

        #pragma unroll
        for (int o = 16; o > 0; o >>= 1) {
            sq  += __shfl_down_sync(0xffffffffu, sq,  o);
            spm += __shfl_down_sync(0xffffffffu, spm, o);
            spp += __shfl_down_sync(0xffffffffu, spp, o);
            cnt += __shfl_down_sync(0xffffffffu, cnt, o);
        }
        if (n == 0)
            g_tpart[task] = make_float4(sq, spm, spp, cnt);
    }

    // ---------------- last-block finalize ----------------
    __syncthreads();
    if (tid == 0) {
        __threadfence();
        unsigned t = atomicAdd(&g_ticket, 1u);
        s_last = (t == TOTAL_BLOCKS - 1);
    }
    __syncthreads();
    if (s_last) {
        __threadfence();
        // dense partials per scale
        double v0 = 0.0, v1 = 0.0, v2 = 0.0;
        v0 = ((volatile double*)g_part)[tid];
        if (tid < NB0D - 256) v0 += ((volatile double*)g_part)[256 + tid];
        if (tid < NB1D) v1 = ((volatile double*)g_part)[NB0D + tid];
        if (tid < NB2D) v2 = ((volatile double*)g_part)[NB0D + NB1D + tid];
        #pragma unroll
        for (int o = 16; o > 0; o >>= 1) {
            v0 += __shfl_down_sync(0xffffffffu, v0, o);
            v1 += __shfl_down_sync(0xffffffffu, v1, o);
            v2 += __shfl_down_sync(0xffffffffu, v2, o);
        }
        if (lane == 0) { dsh[0][wid] = v0; dsh[1][wid] = v1; dsh[2][wid] = v2; }

        // target partials: warp w sums tasks [w*32, w*32+32)
        if (wid < 6) {
            const volatile float* tp = (const volatile float*)g_tpart;
            int o4 = (wid * 32 + lane) * 4;
            double a  = (double)tp[o4 + 0];
            double b  = (double)tp[o4 + 1];
            double c  = (double)tp[o4 + 2];
            double dd = (double)tp[o4 + 3];
            #pragma unroll
            for (int o = 16; o > 0; o >>= 1) {
                a  += __shfl_down_sync(0xffffffffu, a,  o);
                b  += __shfl_down_sync(0xffffffffu, b,  o);
                c  += __shfl_down_sync(0xffffffffu, c,  o);
                dd += __shfl_down_sync(0xffffffffu, dd, o);
            }
            if (lane == 0) { tsh[0][wid] = a; tsh[1][wid] = b; tsh[2][wid] = c; tsh[3][wid] = dd; }
        }
        __syncthreads();

        if (tid == 0) {
            double sall0 = 0.0, sall1 = 0.0, sall2 = 0.0;
            #pragma unroll
            for (int w = 0; w < 8; w++) {
                sall0 += dsh[0][w]; sall1 += dsh[1][w]; sall2 += dsh[2][w];
            }
            const double cells[3] = {4915200.0, 1228800.0, 307200.0};
            double sall[3] = {sall0, sall1, sall2};
            double loss = 0.0;
            #pragma unroll
            for (int s = 0; s < 3; s++) {
                double box = tsh[0][2 * s] + tsh[0][2 * s + 1];
                double pp  = tsh[1][2 * s] + tsh[1][2 * s + 1];
                double pn  = tsh[2][2 * s] + tsh[2][2 * s + 1];
                double np  = tsh[3][2 * s] + tsh[3][2 * s + 1];
                double nn  = cells[s] - np;
                loss += 0.05 * box / np + pp / np + (sall[s] - pn) / nn;
            }
            g_ticket = 0u;           // reset for next replay
            out[0] = (float)loss;
        }
    }
}

extern "C" void kernel_launch(void* const* d_in, const int* in_sizes, int n_in,
                              void* d_out, int out_size) {
    (void)in_sizes; (void)n_in; (void)out_size;
    const float* pred0   = (const float*)d_in[0];
    const float* pred1   = (const float*)d_in[1];
    const float* pred2   = (const float*)d_in[2];
    const float* boxes   = (const float*)d_in[3];
    // d_in[4] = labels (unused, nc==1)
    const float* anchors = (const float*)d_in[5];
    float* out = (float*)d_out;

    yolo_kernel<<<TOTAL_BLOCKS, 256>>>(pred0, pred1, pred2, boxes, anchors, out);
}

// round 15
// speedup vs baseline: 1.0102x; 1.0102x over previous
#include <cuda_runtime.h>
#include <cuda_bf16.h>
#include <cstdint>

// ---------------------------------------------------------------------------
// YOLO loss (nc=1).  B=64, N=32, A=3, grids {160,80,40}, pred [B,18,G,G].
//
// loss = 0.05 * sum_s box_sq[s]/n_pos[s]
//      +        sum_s ( pos_plus[s]/n_pos[s] + (S_all[s]-pos_neg[s])/n_neg[s] )
//
// FINAL FORM (R2-R13 evidence: e2e is pinned by fixed replay overhead +
// ~1TB/s environmental service rate on the mandatory 25.8MB obj-channel
// read; invariant to MLP/occupancy/registers/atomics/TMA/MUFU-count).
//   - single launch (each extra launch costs ~2.2us)
//   - dense pass reads ONLY the objectness channel (1/6 of data), 32-byte
//     ld.global.nc.L2::evict_last.v4.b64, rotating register pipeline
//   - batched-log softplus: 8 EX2 + 1 LG2 per 8 elements
//   - sparse target pass: 192 (scale,batch) warp-tasks, smem dedup
//   - ticket finalize in the last block, accumulators reset for next replay
// ---------------------------------------------------------------------------

#define NN 32
#define TGT_BLOCKS 24
#define NB0D 384
#define NB1D 96
#define NB2D 24
#define DENSE_BLOCKS (NB0D + NB1D + NB2D)          // 504
#define TOTAL_BLOCKS (TGT_BLOCKS + DENSE_BLOCKS)   // 528

__device__ double   g_part[DENSE_BLOCKS];  // dense per-block partials
__device__ float4   g_tpart[192];          // target partials: sq, sp-, sp+, cnt
__device__ unsigned g_ticket;

__device__ __forceinline__ float ex2f(float x) {
    float r; asm("ex2.approx.f32 %0, %1;" : "=f"(r) : "f"(x)); return r;
}
__device__ __forceinline__ float lg2f(float x) {
    float r; asm("lg2.approx.f32 %0, %1;" : "=f"(r) : "f"(x)); return r;
}

struct F8 { float x0, x1, x2, x3, x4, x5, x6, x7; };

// 32-byte L2-pinned load (v4.b64 is the required shape for evict_last on sm_103)
__device__ __forceinline__ F8 ldg_el8(const void* p) {
    unsigned long long r0, r1, r2, r3;
    asm("ld.global.nc.L2::evict_last.v4.b64 {%0,%1,%2,%3}, [%4];"
        : "=l"(r0), "=l"(r1), "=l"(r2), "=l"(r3) : "l"(p));
    F8 v;
    v.x0 = __uint_as_float((unsigned)r0);  v.x1 = __uint_as_float((unsigned)(r0 >> 32));
    v.x2 = __uint_as_float((unsigned)r1);  v.x3 = __uint_as_float((unsigned)(r1 >> 32));
    v.x4 = __uint_as_float((unsigned)r2);  v.x5 = __uint_as_float((unsigned)(r2 >> 32));
    v.x6 = __uint_as_float((unsigned)r3);  v.x7 = __uint_as_float((unsigned)(r3 >> 32));
    return v;
}

__device__ __forceinline__ float sp(float x) {   // target pass only
    return fmaxf(x, 0.0f) + __logf(1.0f + __expf(-fabsf(x)));
}

struct Acc { float ax0, ax1, au0, au1, alg0, alg1; };

#define NL2E (-1.4426950408889634f)

// 8 elements -> 8 EX2 + 1 LG2  (validated rel_err 0.0 since R10)
__device__ __forceinline__ void accum8(F8 a, Acc& c) {
    float u0 = fabsf(a.x0), u1 = fabsf(a.x1), u2 = fabsf(a.x2), u3 = fabsf(a.x3);
    float u4 = fabsf(a.x4), u5 = fabsf(a.x5), u6 = fabsf(a.x6), u7 = fabsf(a.x7);
    float e0 = ex2f(u0 * NL2E), e1 = ex2f(u1 * NL2E);
    float e2 = ex2f(u2 * NL2E), e3 = ex2f(u3 * NL2E);
    float e4 = ex2f(u4 * NL2E), e5 = ex2f(u5 * NL2E);
    float e6 = ex2f(u6 * NL2E), e7 = ex2f(u7 * NL2E);
    float p0 = 1.0f + e0;
    p0 = fmaf(p0, e1, p0);
    p0 = fmaf(p0, e2, p0);
    p0 = fmaf(p0, e3, p0);
    float p1 = 1.0f + e4;
    p1 = fmaf(p1, e5, p1);
    p1 = fmaf(p1, e6, p1);
    p1 = fmaf(p1, e7, p1);
    c.alg0 += lg2f(p0 * p1);
    c.ax0 += (a.x0 + a.x1) + (a.x2 + a.x3);
    c.ax1 += (a.x4 + a.x5) + (a.x6 + a.x7);
    c.au0 += (u0 + u1) + (u2 + u3);
    c.au1 += (u4 + u5) + (u6 + u7);
}

// gathered obj f8 index -> physical byte pointer
// idx = p*HW8 + pos (p = b*3+a) ; phys_f8 = idx + 5*HW8*p + 4*HW8
template <int HW8>
__device__ __forceinline__ const char* objp8(const char* __restrict__ base, int idx) {
    int p = idx / HW8;                       // compile-time magic-mul
    return base + (size_t)(idx + (5 * HW8) * p + 4 * HW8) * 32;
}

// 1600 gathered f8 per block: rotating named-register pipeline.
template <int HW8>
__device__ __forceinline__ void dense1600(const char* __restrict__ base,
                                          int gbase, int tid, Acc& c) {
    int g = gbase + tid;
    F8 a0 = ldg_el8(objp8<HW8>(base, g));
    F8 b0 = ldg_el8(objp8<HW8>(base, g + 256));
    #pragma unroll
    for (int k = 0; k < 2; k++) {
        F8 a1 = ldg_el8(objp8<HW8>(base, g + (2 * k + 2) * 256));
        F8 b1 = ldg_el8(objp8<HW8>(base, g + (2 * k + 3) * 256));
        accum8(a0, c);
        accum8(b0, c);
        a0 = a1; b0 = b1;
    }
    accum8(a0, c);
    accum8(b0, c);
    if (tid < 64)
        accum8(ldg_el8(objp8<HW8>(base, gbase + 1536 + tid)), c);
}

__global__ void __launch_bounds__(256, 4) yolo_kernel(
        const float* __restrict__ pred0,
        const float* __restrict__ pred1,
        const float* __restrict__ pred2,
        const float* __restrict__ boxes,
        const float* __restrict__ anchors,
        float* __restrict__ out) {
    const int bid  = blockIdx.x;
    const int tid  = threadIdx.x;
    const int lane = tid & 31;
    const int wid  = tid >> 5;

    __shared__ float  warpsum[8];
    __shared__ int    keys[8][NN];
    __shared__ double dsh[3][8];
    __shared__ double tsh[4][6];
    __shared__ bool   s_last;

    if (bid >= TGT_BLOCKS) {
        // ---------------- dense objectness pass ----------------
        const int d = bid - TGT_BLOCKS;
        Acc a = {0.0f, 0.0f, 0.0f, 0.0f, 0.0f, 0.0f};
        if (d < NB0D) {
            dense1600<3200>((const char*)pred0, d * 1600, tid, a);
        } else if (d < NB0D + NB1D) {
            dense1600< 800>((const char*)pred1, (d - NB0D) * 1600, tid, a);
        } else {
            dense1600< 200>((const char*)pred2, (d - NB0D - NB1D) * 1600, tid, a);
        }
        float v = 0.5f * ((a.ax0 + a.ax1) + (a.au0 + a.au1))
                + 0.69314718055994531f * (a.alg0 + a.alg1);

        #pragma unroll
        for (int o = 16; o > 0; o >>= 1)
            v += __shfl_down_sync(0xffffffffu, v, o);
        if (lane == 0) warpsum[wid] = v;
        __syncthreads();
        if (tid == 0) {
            double t = 0.0;
            #pragma unroll
            for (int w = 0; w < 8; w++) t += (double)warpsum[w];
            g_part[d] = t;
        }
    } else {
        // ---------------- sparse target pass: one (scale,batch) per warp ----------------
        const int task = bid * 8 + wid;          // 0..191
        const int s = task >> 6;
        const int b = task & 63;
        const int n = lane;

        const int G = (s == 0) ? 160 : (s == 1) ? 80 : 40;
        const float* pred = (s == 0) ? pred0 : (s == 1) ? pred1 : pred2;
        const int HW = G * G;

        float4 bx = reinterpret_cast<const float4*>(boxes)[b * NN + n];
        float gx = bx.x * (float)G;
        float gy = bx.y * (float)G;
        float gw = bx.z * (float)G;
        float gh = bx.w * (float)G;
        int gi = (int)gx;
        int gj = (int)gy;

        // anchor matching: argmax over a of prod(min(r,1/r)), first-max tiebreak
        float bestIou = -1.0f;
        float aw = 1.0f, ah = 1.0f;
        int best = 0;
        #pragma unroll
        for (int a = 0; a < 3; a++) {
            float Aw = anchors[s * 6 + a * 2 + 0];
            float Ah = anchors[s * 6 + a * 2 + 1];
            float rw = __fdiv_rn(Aw, gw);
            float rh = __fdiv_rn(Ah, gh);
            float iw = fminf(rw, __fdiv_rn(1.0f, rw));
            float ih = fminf(rh, __fdiv_rn(1.0f, rh));
            float iou = iw * ih;
            if (iou > bestIou) { bestIou = iou; best = a; aw = Aw; ah = Ah; }
        }

        // dedup: last write wins -> entry n live iff no later n' has same key
        int key = (best * G + gj) * G + gi;
        keys[wid][n] = key;
        __syncwarp();
        bool live = true;
        for (int m = n + 1; m < NN; m++)
            if (keys[wid][m] == key) { live = false; break; }

        float sq = 0.0f, spp = 0.0f, spm = 0.0f, cnt = 0.0f;
        if (live) {
            size_t base = (size_t)(b * 18 + best * 6) * HW + (size_t)gj * G + gi;
            float p0 = __ldg(pred + base);
            float p1 = __ldg(pred + base + (size_t)HW);
            float p2 = __ldg(pred + base + (size_t)2 * HW);
            float p3 = __ldg(pred + base + (size_t)3 * HW);
            float p4 = __ldg(pred + base + (size_t)4 * HW);

            float tx = gx - (float)gi;
            float ty = gy - (float)gj;
            float tw = logf(__fdiv_rn(gw, aw) + 1e-16f);
            float th = logf(__fdiv_rn(gh, ah) + 1e-16f);

            float d0 = p0 - tx, d1 = p1 - ty, d2 = p2 - tw, d3 = p3 - th;
            sq  = d0 * d0 + d1 * d1 + d2 * d2 + d3 * d3;
            spm = sp(-p4);
            spp = sp(p4);
            cnt = 1.0f;
        }

        #pragma unroll
        for (int o = 16; o > 0; o >>= 1) {
            sq  += __shfl_down_sync(0xffffffffu, sq,  o);
            spm += __shfl_down_sync(0xffffffffu, spm, o);
            spp += __shfl_down_sync(0xffffffffu, spp, o);
            cnt += __shfl_down_sync(0xffffffffu, cnt, o);
        }
        if (n == 0)
            g_tpart[task] = make_float4(sq, spm, spp, cnt);
    }

    // ---------------- last-block finalize ----------------
    __syncthreads();
    if (tid == 0) {
        __threadfence();
        unsigned t = atomicAdd(&g_ticket, 1u);
        s_last = (t == TOTAL_BLOCKS - 1);
    }
    __syncthreads();
    if (s_last) {
        __threadfence();
        // issue ALL finalize loads up front (dense partials + target partials)
        double v0 = ((volatile double*)g_part)[tid];
        double v0b = (tid < NB0D - 256) ? ((volatile double*)g_part)[256 + tid] : 0.0;
        double v1 = (tid < NB1D) ? ((volatile double*)g_part)[NB0D + tid] : 0.0;
        double v2 = (tid < NB2D) ? ((volatile double*)g_part)[NB0D + NB1D + tid] : 0.0;
        double ta = 0.0, tb = 0.0, tc = 0.0, td = 0.0;
        if (wid < 6) {
            const volatile float* tp = (const volatile float*)g_tpart;
            int o4 = (wid * 32 + lane) * 4;
            ta = (double)tp[o4 + 0];
            tb = (double)tp[o4 + 1];
            tc = (double)tp[o4 + 2];
            td = (double)tp[o4 + 3];
        }
        v0 += v0b;
        #pragma unroll
        for (int o = 16; o > 0; o >>= 1) {
            v0 += __shfl_down_sync(0xffffffffu, v0, o);
            v1 += __shfl_down_sync(0xffffffffu, v1, o);
            v2 += __shfl_down_sync(0xffffffffu, v2, o);
            ta += __shfl_down_sync(0xffffffffu, ta, o);
            tb += __shfl_down_sync(0xffffffffu, tb, o);
            tc += __shfl_down_sync(0xffffffffu, tc, o);
            td += __shfl_down_sync(0xffffffffu, td, o);
        }
        if (lane == 0) {
            dsh[0][wid] = v0; dsh[1][wid] = v1; dsh[2][wid] = v2;
            if (wid < 6) { tsh[0][wid] = ta; tsh[1][wid] = tb; tsh[2][wid] = tc; tsh[3][wid] = td; }
        }
        __syncthreads();

        if (tid == 0) {
            double sall0 = 0.0, sall1 = 0.0, sall2 = 0.0;
            #pragma unroll
            for (int w = 0; w < 8; w++) {
                sall0 += dsh[0][w]; sall1 += dsh[1][w]; sall2 += dsh[2][w];
            }
            const double cells[3] = {4915200.0, 1228800.0, 307200.0};
            double sall[3] = {sall0, sall1, sall2};
            double loss = 0.0;
            #pragma unroll
            for (int s = 0; s < 3; s++) {
                double box = tsh[0][2 * s] + tsh[0][2 * s + 1];
                double pp  = tsh[1][2 * s] + tsh[1][2 * s + 1];
                double pn  = tsh[2][2 * s] + tsh[2][2 * s + 1];
                double np  = tsh[3][2 * s] + tsh[3][2 * s + 1];
                double nn  = cells[s] - np;
                loss += 0.05 * box / np + pp / np + (sall[s] - pn) / nn;
            }
            g_ticket = 0u;           // reset for next replay
            out[0] = (float)loss;
        }
    }
}

extern "C" void kernel_launch(void* const* d_in, const int* in_sizes, int n_in,
                              void* d_out, int out_size) {
    (void)in_sizes; (void)n_in; (void)out_size;
    const float* pred0   = (const float*)d_in[0];
    const float* pred1   = (const float*)d_in[1];
    const float* pred2   = (const float*)d_in[2];
    const float* boxes   = (const float*)d_in[3];
    // d_in[4] = labels (unused, nc==1)
    const float* anchors = (const float*)d_in[5];
    float* out = (float*)d_out;

    yolo_kernel<<<TOTAL_BLOCKS, 256>>>(pred0, pred1, pred2, boxes, anchors, out);
}